// round 1
// baseline (speedup 1.0000x reference)
#include <cuda_runtime.h>
#include <cuda_bf16.h>
#include <cstdint>

// Shapes (fixed by the problem)
#define BATCH    2
#define SEQ      2048
#define DMODEL   1024
#define NHEADS   16
#define HEADDIM  64
#define MROWS    (BATCH * SEQ)        // 4096
#define BH       (BATCH * NHEADS)     // 32

// Scratch (device globals — no allocation allowed)
__device__ float g_q[BH * SEQ * HEADDIM];     // [bh][s][dh]
__device__ float g_k[BH * SEQ * HEADDIM];
__device__ float g_v[BH * SEQ * HEADDIM];
__device__ float g_ctx[BATCH * SEQ * DMODEL]; // [b][s][d]

// ---------------------------------------------------------------------------
// GEMM: out = A[M,K] @ W[N,K]^T + bias, M=4096, N=K=1024.
// sel 0/1/2 -> write to g_q/g_k/g_v with [bh][s][dh] layout
// sel 3     -> write plain [M,N] to outext
// Aext == nullptr -> read from g_ctx.
// 128x128 tile, BK=8, 256 threads, 8x8 per-thread microtile.
// ---------------------------------------------------------------------------
__global__ void __launch_bounds__(256) gemm_bias_kernel(
    const float* __restrict__ Aext, const float* __restrict__ W,
    const float* __restrict__ bias, float* __restrict__ outext, int sel)
{
    __shared__ float As[8][128];
    __shared__ float Ws[8][128];

    const float* A = Aext ? Aext : g_ctx;
    float* out;
    if (sel == 0)      out = g_q;
    else if (sel == 1) out = g_k;
    else if (sel == 2) out = g_v;
    else               out = outext;

    const int K = 1024;
    const int bm = blockIdx.y * 128;
    const int bn = blockIdx.x * 128;
    const int tid = threadIdx.x;
    const int tx = tid & 15, ty = tid >> 4;

    const int lr = tid >> 1;           // 0..127
    const int lc = (tid & 1) << 2;     // 0 or 4

    float acc[8][8];
#pragma unroll
    for (int i = 0; i < 8; i++)
#pragma unroll
        for (int j = 0; j < 8; j++) acc[i][j] = 0.f;

    const float* Aptr = A + (size_t)(bm + lr) * K + lc;
    const float* Wptr = W + (size_t)(bn + lr) * K + lc;

    for (int k0 = 0; k0 < K; k0 += 8) {
        float4 a4 = *(const float4*)(Aptr + k0);
        float4 w4 = *(const float4*)(Wptr + k0);
        As[lc + 0][lr] = a4.x; As[lc + 1][lr] = a4.y;
        As[lc + 2][lr] = a4.z; As[lc + 3][lr] = a4.w;
        Ws[lc + 0][lr] = w4.x; Ws[lc + 1][lr] = w4.y;
        Ws[lc + 2][lr] = w4.z; Ws[lc + 3][lr] = w4.w;
        __syncthreads();
#pragma unroll
        for (int kk = 0; kk < 8; kk++) {
            float a[8], w[8];
            *(float4*)&a[0] = *(const float4*)&As[kk][ty * 8];
            *(float4*)&a[4] = *(const float4*)&As[kk][ty * 8 + 4];
            *(float4*)&w[0] = *(const float4*)&Ws[kk][tx * 8];
            *(float4*)&w[4] = *(const float4*)&Ws[kk][tx * 8 + 4];
#pragma unroll
            for (int i = 0; i < 8; i++)
#pragma unroll
                for (int j = 0; j < 8; j++)
                    acc[i][j] = fmaf(a[i], w[j], acc[i][j]);
        }
        __syncthreads();
    }

    const int n0 = bn + tx * 8;
    float bv[8];
    *(float4*)&bv[0] = *(const float4*)(bias + n0);
    *(float4*)&bv[4] = *(const float4*)(bias + n0 + 4);

#pragma unroll
    for (int i = 0; i < 8; i++) {
        const int m = bm + ty * 8 + i;
        float4 r0 = make_float4(acc[i][0] + bv[0], acc[i][1] + bv[1],
                                acc[i][2] + bv[2], acc[i][3] + bv[3]);
        float4 r1 = make_float4(acc[i][4] + bv[4], acc[i][5] + bv[5],
                                acc[i][6] + bv[6], acc[i][7] + bv[7]);
        float* dst;
        if (sel < 3) {
            // [bh][s][dh]: bh = b*16 + h,  n0..n0+7 stays inside one head
            const int b = m >> 11, s = m & 2047;
            const int h = n0 >> 6, dh = n0 & 63;
            dst = out + ((size_t)(b * NHEADS + h)) * (SEQ * HEADDIM)
                      + (size_t)s * HEADDIM + dh;
        } else {
            dst = out + (size_t)m * DMODEL + n0;
        }
        *(float4*)dst       = r0;
        *(float4*)(dst + 4) = r1;
    }
}

// ---------------------------------------------------------------------------
// Causal flash attention over g_q/g_k/g_v -> g_ctx ([B,S,D]).
// CTA: 64 q-rows x full head dim (64). 256 threads = 16x16; 4x4 microtiles.
// Dynamic smem: Qs/Ks/Vt/Ps each 64x68 floats (pad 68 = conflict-free + 16B
// aligned float4), plus per-row m/l state.
// ---------------------------------------------------------------------------
#define AST 68                                  // smem row stride (floats)
#define ATTN_SMEM ((4 * 64 * AST + 128) * 4)    // bytes

__global__ void __launch_bounds__(256) attn_kernel()
{
    extern __shared__ float sm[];
    float* Qs = sm;
    float* Ks = sm + 64 * AST;
    float* Vt = sm + 2 * 64 * AST;
    float* Ps = sm + 3 * 64 * AST;
    float* rm = sm + 4 * 64 * AST;
    float* rl = rm + 64;

    const int qt  = blockIdx.x;          // 0..31
    const int bh  = blockIdx.y;          // 0..31
    const int b   = bh >> 4, h = bh & 15;
    const int tid = threadIdx.x;
    const int tx  = tid & 15, ty = tid >> 4;

    // Load Q tile, pre-scaled by 1/sqrt(64)
    const float* qb = g_q + (size_t)bh * (SEQ * HEADDIM) + (size_t)qt * 64 * HEADDIM;
#pragma unroll
    for (int it = 0; it < 4; it++) {
        const int i = tid + it * 256;
        const int r = i >> 4, c4 = (i & 15) << 2;
        float4 v4 = *(const float4*)(qb + r * HEADDIM + c4);
        v4.x *= 0.125f; v4.y *= 0.125f; v4.z *= 0.125f; v4.w *= 0.125f;
        *(float4*)&Qs[r * AST + c4] = v4;
    }
    if (tid < 64) { rm[tid] = -1e30f; rl[tid] = 0.f; }

    float o[4][4];
#pragma unroll
    for (int i = 0; i < 4; i++)
#pragma unroll
        for (int j = 0; j < 4; j++) o[i][j] = 0.f;

    __syncthreads();

    for (int kt = 0; kt <= qt; kt++) {
        const float* kb = g_k + (size_t)bh * (SEQ * HEADDIM) + (size_t)kt * 64 * HEADDIM;
        const float* vb = g_v + (size_t)bh * (SEQ * HEADDIM) + (size_t)kt * 64 * HEADDIM;
#pragma unroll
        for (int it = 0; it < 4; it++) {
            const int i = tid + it * 256;
            const int r = i >> 4, c4 = (i & 15) << 2;
            *(float4*)&Ks[r * AST + c4] = *(const float4*)(kb + r * HEADDIM + c4);
            float4 vv = *(const float4*)(vb + r * HEADDIM + c4);
            Vt[(c4 + 0) * AST + r] = vv.x;     // transpose: Vt[dh][k]
            Vt[(c4 + 1) * AST + r] = vv.y;
            Vt[(c4 + 2) * AST + r] = vv.z;
            Vt[(c4 + 3) * AST + r] = vv.w;
        }
        __syncthreads();

        // S = (Q/8) K^T  -- 4x4 per thread, float4 along d
        float s[4][4];
#pragma unroll
        for (int i = 0; i < 4; i++)
#pragma unroll
            for (int j = 0; j < 4; j++) s[i][j] = 0.f;
#pragma unroll
        for (int d4 = 0; d4 < 16; d4++) {
            float4 qv[4], kv[4];
#pragma unroll
            for (int i = 0; i < 4; i++)
                qv[i] = *(const float4*)&Qs[(ty * 4 + i) * AST + d4 * 4];
#pragma unroll
            for (int j = 0; j < 4; j++)
                kv[j] = *(const float4*)&Ks[(tx * 4 + j) * AST + d4 * 4];
#pragma unroll
            for (int i = 0; i < 4; i++)
#pragma unroll
                for (int j = 0; j < 4; j++)
                    s[i][j] += qv[i].x * kv[j].x + qv[i].y * kv[j].y
                             + qv[i].z * kv[j].z + qv[i].w * kv[j].w;
        }

        if (kt == qt) {   // causal mask on the diagonal tile only
#pragma unroll
            for (int i = 0; i < 4; i++)
#pragma unroll
                for (int j = 0; j < 4; j++)
                    if (tx * 4 + j > ty * 4 + i) s[i][j] = -1e30f;
        }

        // Online softmax update
        float mnew[4], lsum[4], scl[4];
#pragma unroll
        for (int i = 0; i < 4; i++) {
            float mx = fmaxf(fmaxf(s[i][0], s[i][1]), fmaxf(s[i][2], s[i][3]));
            mx = fmaxf(mx, __shfl_xor_sync(0xffffffffu, mx, 1));
            mx = fmaxf(mx, __shfl_xor_sync(0xffffffffu, mx, 2));
            mx = fmaxf(mx, __shfl_xor_sync(0xffffffffu, mx, 4));
            mx = fmaxf(mx, __shfl_xor_sync(0xffffffffu, mx, 8));
            const float mprev = rm[ty * 4 + i];
            const float mn = fmaxf(mprev, mx);
            float ls = 0.f;
#pragma unroll
            for (int j = 0; j < 4; j++) {
                s[i][j] = __expf(s[i][j] - mn);
                ls += s[i][j];
            }
            ls += __shfl_xor_sync(0xffffffffu, ls, 1);
            ls += __shfl_xor_sync(0xffffffffu, ls, 2);
            ls += __shfl_xor_sync(0xffffffffu, ls, 4);
            ls += __shfl_xor_sync(0xffffffffu, ls, 8);
            mnew[i] = mn; lsum[i] = ls;
            scl[i] = __expf(mprev - mn);
        }

#pragma unroll
        for (int i = 0; i < 4; i++)
            *(float4*)&Ps[(ty * 4 + i) * AST + tx * 4] =
                make_float4(s[i][0], s[i][1], s[i][2], s[i][3]);
#pragma unroll
        for (int i = 0; i < 4; i++)
#pragma unroll
            for (int j = 0; j < 4; j++) o[i][j] *= scl[i];

        __syncwarp();                      // all lanes done reading rm/rl
        if (tx == 0) {
#pragma unroll
            for (int i = 0; i < 4; i++) {
                const int r = ty * 4 + i;
                rm[r] = mnew[i];
                rl[r] = rl[r] * scl[i] + lsum[i];
            }
        }
        __syncthreads();                   // Ps visible, rm/rl ordered

        // O += P @ V  (via Vt, float4 along k)
#pragma unroll
        for (int k4 = 0; k4 < 16; k4++) {
            float4 pv[4], vv[4];
#pragma unroll
            for (int i = 0; i < 4; i++)
                pv[i] = *(const float4*)&Ps[(ty * 4 + i) * AST + k4 * 4];
#pragma unroll
            for (int j = 0; j < 4; j++)
                vv[j] = *(const float4*)&Vt[(tx * 4 + j) * AST + k4 * 4];
#pragma unroll
            for (int i = 0; i < 4; i++)
#pragma unroll
                for (int j = 0; j < 4; j++)
                    o[i][j] += pv[i].x * vv[j].x + pv[i].y * vv[j].y
                             + pv[i].z * vv[j].z + pv[i].w * vv[j].w;
        }
        __syncthreads();                   // before overwriting Ks/Vt/Ps
    }

    // Normalize and write ctx[b][s][h*64+dh]
#pragma unroll
    for (int i = 0; i < 4; i++) {
        const float inv = 1.f / rl[ty * 4 + i];
        const int qg = qt * 64 + ty * 4 + i;
        float* dst = g_ctx + ((size_t)b * SEQ + qg) * DMODEL + h * HEADDIM + tx * 4;
        *(float4*)dst = make_float4(o[i][0] * inv, o[i][1] * inv,
                                    o[i][2] * inv, o[i][3] * inv);
    }
}

// ---------------------------------------------------------------------------
// Launch. Inputs (metadata order): Q,K,V,attn_mask,padding_mask,
// Wq,bq,Wk,bk,Wv,bv,Wo,bo. Masks are the fixed causal/no-padding case and
// are implemented structurally in attn_kernel.
// ---------------------------------------------------------------------------
extern "C" void kernel_launch(void* const* d_in, const int* in_sizes, int n_in,
                              void* d_out, int out_size)
{
    (void)in_sizes; (void)n_in; (void)out_size;
    const float* Q  = (const float*)d_in[0];
    const float* K  = (const float*)d_in[1];
    const float* V  = (const float*)d_in[2];
    const float* Wq = (const float*)d_in[5];
    const float* bq = (const float*)d_in[6];
    const float* Wk = (const float*)d_in[7];
    const float* bk = (const float*)d_in[8];
    const float* Wv = (const float*)d_in[9];
    const float* bv = (const float*)d_in[10];
    const float* Wo = (const float*)d_in[11];
    const float* bo = (const float*)d_in[12];
    float* out = (float*)d_out;

    cudaFuncSetAttribute(attn_kernel,
                         cudaFuncAttributeMaxDynamicSharedMemorySize, ATTN_SMEM);

    dim3 gg(DMODEL / 128, MROWS / 128);   // (8, 32)
    gemm_bias_kernel<<<gg, 256>>>(Q, Wq, bq, nullptr, 0);
    gemm_bias_kernel<<<gg, 256>>>(K, Wk, bk, nullptr, 1);
    gemm_bias_kernel<<<gg, 256>>>(V, Wv, bv, nullptr, 2);
    attn_kernel<<<dim3(SEQ / 64, BH), 256, ATTN_SMEM>>>();
    gemm_bias_kernel<<<gg, 256>>>(nullptr, Wo, bo, out, 3);
}